// round 4
// baseline (speedup 1.0000x reference)
#include <cuda_runtime.h>

// ---------------------------------------------------------------------------
// Sparse 3D CNN (submanifold conv + masked maxpool pyramid), fp32.
// 64^3 -> 1^3, channels 3 -> 256.
// Heavy layers use packed fma.rn.f32x2 (2 MACs per fma-pipe slot, sm_100+).
// ---------------------------------------------------------------------------

#define VOL0 (64 * 64 * 64)
#define MAXE (64 * 64 * 64 * 64)

__device__ float g_bufA[MAXE];
__device__ float g_bufB[MAXE];
__device__ float g_maskA[VOL0];
__device__ float g_maskB[VOL0];
__device__ int   g_owner[VOL0];
__device__ int   g_list[VOL0];
__device__ int   g_cnt;

typedef unsigned long long u64t;

__device__ __forceinline__ u64t pack2(float lo, float hi) {
    u64t r;
    asm("mov.b64 %0, {%1, %2};" : "=l"(r) : "f"(lo), "f"(hi));
    return r;
}
__device__ __forceinline__ u64t bcast2(float v) {
    u64t r;
    asm("mov.b64 %0, {%1, %1};" : "=l"(r) : "f"(v));
    return r;
}
__device__ __forceinline__ void fma2(u64t& d, u64t a, u64t b) {
    asm("fma.rn.f32x2 %0, %1, %2, %0;" : "+l"(d) : "l"(a), "l"(b));
}
__device__ __forceinline__ void unpack2(float& lo, float& hi, u64t v) {
    asm("mov.b64 {%0, %1}, %2;" : "=f"(lo), "=f"(hi) : "l"(v));
}

// ---------------------------------------------------------------------------
__global__ void k_reset(int* __restrict__ owner) {
    int i = blockIdx.x * blockDim.x + threadIdx.x;
    if (i == 0) g_cnt = 0;
    if (i < VOL0) owner[i] = -1;
}

__global__ void k_scatter(const int* __restrict__ coors, int n, int* __restrict__ owner) {
    int i = blockIdx.x * blockDim.x + threadIdx.x;
    if (i >= n) return;
    int z = coors[3 * i], y = coors[3 * i + 1], x = coors[3 * i + 2];
    atomicMax(&owner[(z * 64 + y) * 64 + x], i);  // last-write-wins
}

__global__ void k_build(const int* __restrict__ owner, const float* __restrict__ feat,
                        float* __restrict__ A, float* __restrict__ mask) {
    int v = blockIdx.x * blockDim.x + threadIdx.x;
    if (v >= VOL0) return;
    int o = owner[v];
    if (o >= 0) {
        mask[v] = 1.0f;
        A[3 * v + 0] = feat[3 * o + 0];
        A[3 * v + 1] = feat[3 * o + 1];
        A[3 * v + 2] = feat[3 * o + 2];
        int p = atomicAdd(&g_cnt, 1);
        g_list[p] = v;
    } else {
        mask[v] = 0.0f;
        A[3 * v + 0] = 0.0f;
        A[3 * v + 1] = 0.0f;
        A[3 * v + 2] = 0.0f;
    }
}

__global__ void k_fill0(float4* __restrict__ p, int n4) {
    int i = blockIdx.x * blockDim.x + threadIdx.x;
    if (i < n4) p[i] = make_float4(0.f, 0.f, 0.f, 0.f);
}

// ---------------------------------------------------------------------------
// Sparse conv 3 -> 64 at level 0 (small; scalar path).
// ---------------------------------------------------------------------------
__global__ void __launch_bounds__(128) k_conv_s0(
    const float* __restrict__ in, float* __restrict__ out,
    const float* __restrict__ W) {
    constexpr int VT = 10;
    const int lane = threadIdx.x & 31;
    const int vg = threadIdx.x >> 5;
    const int cnt = g_cnt;
    const int base = blockIdx.x * (4 * VT) + vg * VT;
    if (blockIdx.x * (4 * VT) >= cnt) return;

    int vids[VT];
#pragma unroll
    for (int i = 0; i < VT; i++) {
        int p = base + i;
        vids[i] = (p < cnt) ? g_list[p] : -1;
    }

    float2 acc[VT];
#pragma unroll
    for (int i = 0; i < VT; i++) { acc[i].x = 0.f; acc[i].y = 0.f; }

#pragma unroll 1
    for (int tap = 0; tap < 27; ++tap) {
        const int dz = tap / 9 - 1;
        const int dy = (tap / 3) % 3 - 1;
        const int dx = tap % 3 - 1;
        const float2* wp = reinterpret_cast<const float2*>(W + tap * 3 * 64) + lane;
        float2 w0 = wp[0], w1 = wp[32], w2 = wp[64];

        int offs[VT];
        bool val[VT];
#pragma unroll
        for (int i = 0; i < VT; i++) {
            int v = vids[i];
            int zz = (v >> 12) + dz, yy = ((v >> 6) & 63) + dy, xx = (v & 63) + dx;
            val[i] = (v >= 0) & ((unsigned)zz < 64u) & ((unsigned)yy < 64u) &
                     ((unsigned)xx < 64u);
            offs[i] = ((zz * 64 + yy) * 64 + xx) * 3;
        }
#pragma unroll
        for (int i = 0; i < VT; i++) {
            float a0 = val[i] ? in[offs[i] + 0] : 0.f;
            float a1 = val[i] ? in[offs[i] + 1] : 0.f;
            float a2 = val[i] ? in[offs[i] + 2] : 0.f;
            acc[i].x = fmaf(a0, w0.x, acc[i].x);
            acc[i].y = fmaf(a0, w0.y, acc[i].y);
            acc[i].x = fmaf(a1, w1.x, acc[i].x);
            acc[i].y = fmaf(a1, w1.y, acc[i].y);
            acc[i].x = fmaf(a2, w2.x, acc[i].x);
            acc[i].y = fmaf(a2, w2.y, acc[i].y);
        }
    }

#pragma unroll
    for (int i = 0; i < VT; i++)
        if (vids[i] >= 0)
            *reinterpret_cast<float2*>(out + vids[i] * 64 + 2 * lane) = acc[i];
}

// ---------------------------------------------------------------------------
// Sparse conv 64 -> 64 at level 0 (10.6 GMAC) — f32x2 packed over voxel pairs.
// Lane -> cout pair (2*lane, 2*lane+1); warp -> VT=10 voxels (5 pairs).
// ---------------------------------------------------------------------------
__global__ void __launch_bounds__(128) k_conv_s64(
    const float* __restrict__ in, float* __restrict__ out,
    const float* __restrict__ W) {
    constexpr int VT = 10;
    constexpr int NP = VT / 2;
    const int lane = threadIdx.x & 31;
    const int vg = threadIdx.x >> 5;
    const int cnt = g_cnt;
    const int base = blockIdx.x * (4 * VT) + vg * VT;
    if (blockIdx.x * (4 * VT) >= cnt) return;

    int vids[VT];
#pragma unroll
    for (int i = 0; i < VT; i++) {
        int p = base + i;
        vids[i] = (p < cnt) ? g_list[p] : -1;
    }

    u64t acc0[NP], acc1[NP];  // acc0: cout 2*lane, acc1: cout 2*lane+1 (x2 voxels)
#pragma unroll
    for (int p = 0; p < NP; p++) { acc0[p] = 0ull; acc1[p] = 0ull; }

#pragma unroll 1
    for (int tap = 0; tap < 27; ++tap) {
        const int dz = tap / 9 - 1;
        const int dy = (tap / 3) % 3 - 1;
        const int dx = tap % 3 - 1;
        const float2* wp = reinterpret_cast<const float2*>(W + tap * 64 * 64) + lane;

        int offs[VT];
        bool val[VT];
#pragma unroll
        for (int i = 0; i < VT; i++) {
            int v = vids[i];
            int zz = (v >> 12) + dz, yy = ((v >> 6) & 63) + dy, xx = (v & 63) + dx;
            val[i] = (v >= 0) & ((unsigned)zz < 64u) & ((unsigned)yy < 64u) &
                     ((unsigned)xx < 64u);
            offs[i] = ((zz * 64 + yy) * 64 + xx) * 64;
        }

#pragma unroll 1
        for (int c = 0; c < 64; c += 4) {
            float2 w0 = wp[(c + 0) * 32];
            float2 w1 = wp[(c + 1) * 32];
            float2 w2 = wp[(c + 2) * 32];
            float2 w3 = wp[(c + 3) * 32];
            u64t wx0 = bcast2(w0.x), wy0 = bcast2(w0.y);
            u64t wx1 = bcast2(w1.x), wy1 = bcast2(w1.y);
            u64t wx2 = bcast2(w2.x), wy2 = bcast2(w2.y);
            u64t wx3 = bcast2(w3.x), wy3 = bcast2(w3.y);
#pragma unroll
            for (int p = 0; p < NP; p++) {
                float4 ai = val[2 * p]
                    ? *reinterpret_cast<const float4*>(in + offs[2 * p] + c)
                    : make_float4(0.f, 0.f, 0.f, 0.f);
                float4 aj = val[2 * p + 1]
                    ? *reinterpret_cast<const float4*>(in + offs[2 * p + 1] + c)
                    : make_float4(0.f, 0.f, 0.f, 0.f);
                u64t pa;
                pa = pack2(ai.x, aj.x); fma2(acc0[p], pa, wx0); fma2(acc1[p], pa, wy0);
                pa = pack2(ai.y, aj.y); fma2(acc0[p], pa, wx1); fma2(acc1[p], pa, wy1);
                pa = pack2(ai.z, aj.z); fma2(acc0[p], pa, wx2); fma2(acc1[p], pa, wy2);
                pa = pack2(ai.w, aj.w); fma2(acc0[p], pa, wx3); fma2(acc1[p], pa, wy3);
            }
        }
    }

#pragma unroll
    for (int p = 0; p < NP; p++) {
        float a0, a1, b0, b1;
        unpack2(a0, a1, acc0[p]);
        unpack2(b0, b1, acc1[p]);
        if (vids[2 * p] >= 0) {
            float2 t; t.x = a0; t.y = b0;
            *reinterpret_cast<float2*>(out + vids[2 * p] * 64 + 2 * lane) = t;
        }
        if (vids[2 * p + 1] >= 0) {
            float2 t; t.x = a1; t.y = b1;
            *reinterpret_cast<float2*>(out + vids[2 * p + 1] * 64 + 2 * lane) = t;
        }
    }
}

// ---------------------------------------------------------------------------
// Dense conv, f32x2 packed over x-position pairs. Block = 32*WX*WC threads.
// Thread: XP x-pairs (XTT=2*XP x-positions), COT couts.
// CONTIG: couts contiguous per thread (float2 weight/output when COT==2).
// ---------------------------------------------------------------------------
template <int CIN, int COUT, int WX, int WC, int COT, int XP, bool CONTIG>
__global__ void __launch_bounds__(32 * WX * WC) k_convp(
    const float* __restrict__ in, float* __restrict__ out,
    const float* __restrict__ W, const float* __restrict__ mask, int D) {
    constexpr int XTT = 2 * XP;
    const int lane = threadIdx.x & 31;
    const int wrp = threadIdx.x >> 5;
    const int wc = wrp % WC;
    const int wx = wrp / WC;
    const int z = blockIdx.z, y = blockIdx.y;
    const int x0 = blockIdx.x * (WX * XTT) + wx * XTT;
    const int co0 = CONTIG ? (lane + 32 * wc) * COT : (lane + 32 * wc);

    u64t acc[XP][COT];
#pragma unroll
    for (int p = 0; p < XP; p++)
#pragma unroll
        for (int j = 0; j < COT; j++) acc[p][j] = 0ull;

#pragma unroll 1
    for (int r = 0; r < 9; r++) {
        const int dz = r / 3 - 1, dy = r % 3 - 1;
        const int zz = z + dz, yy = y + dy;
        if ((unsigned)zz >= (unsigned)D || (unsigned)yy >= (unsigned)D) continue;
        const float* rowp = in + (size_t)((zz * D + yy) * D) * CIN;
#pragma unroll 1
        for (int dx = 0; dx < 3; dx++) {
            const float* wp = W + (size_t)((r * 3 + dx) * CIN) * COUT + co0;
            int offs[XTT];
            bool val[XTT];
#pragma unroll
            for (int i = 0; i < XTT; i++) {
                int gx = x0 + i + dx - 1;
                val[i] = (unsigned)gx < (unsigned)D;
                offs[i] = gx * CIN;
            }
#pragma unroll 1
            for (int c = 0; c < CIN; c += 4) {
                u64t wb[4][COT];
#pragma unroll
                for (int q = 0; q < 4; q++) {
                    if (CONTIG && COT == 2) {
                        float2 t = *reinterpret_cast<const float2*>(wp + (c + q) * COUT);
                        wb[q][0] = bcast2(t.x);
                        wb[q][1] = bcast2(t.y);
                    } else {
#pragma unroll
                        for (int j = 0; j < COT; j++)
                            wb[q][j] = bcast2(wp[(c + q) * COUT + j * 32 * WC]);
                    }
                }
#pragma unroll
                for (int p = 0; p < XP; p++) {
                    float4 ai = val[2 * p]
                        ? *reinterpret_cast<const float4*>(rowp + offs[2 * p] + c)
                        : make_float4(0.f, 0.f, 0.f, 0.f);
                    float4 aj = val[2 * p + 1]
                        ? *reinterpret_cast<const float4*>(rowp + offs[2 * p + 1] + c)
                        : make_float4(0.f, 0.f, 0.f, 0.f);
                    u64t pa;
                    pa = pack2(ai.x, aj.x);
#pragma unroll
                    for (int j = 0; j < COT; j++) fma2(acc[p][j], pa, wb[0][j]);
                    pa = pack2(ai.y, aj.y);
#pragma unroll
                    for (int j = 0; j < COT; j++) fma2(acc[p][j], pa, wb[1][j]);
                    pa = pack2(ai.z, aj.z);
#pragma unroll
                    for (int j = 0; j < COT; j++) fma2(acc[p][j], pa, wb[2][j]);
                    pa = pack2(ai.w, aj.w);
#pragma unroll
                    for (int j = 0; j < COT; j++) fma2(acc[p][j], pa, wb[3][j]);
                }
            }
        }
    }

    const int vb = (z * D + y) * D;
#pragma unroll
    for (int p = 0; p < XP; p++) {
        float lo[COT], hi[COT];
#pragma unroll
        for (int j = 0; j < COT; j++) unpack2(lo[j], hi[j], acc[p][j]);
        int gx0 = x0 + 2 * p;
        float m0 = mask[vb + gx0];
        float m1 = mask[vb + gx0 + 1];
        float* op0 = out + (size_t)(vb + gx0) * COUT + co0;
        float* op1 = out + (size_t)(vb + gx0 + 1) * COUT + co0;
        if (CONTIG && COT == 2) {
            float2 t0; t0.x = lo[0] * m0; t0.y = lo[1] * m0;
            float2 t1; t1.x = hi[0] * m1; t1.y = hi[1] * m1;
            *reinterpret_cast<float2*>(op0) = t0;
            *reinterpret_cast<float2*>(op1) = t1;
        } else {
#pragma unroll
            for (int j = 0; j < COT; j++) {
                op0[j * 32 * WC] = lo[j] * m0;
                op1[j * 32 * WC] = hi[j] * m1;
            }
        }
    }
}

// ---------------------------------------------------------------------------
// Dense conv, scalar (tail layers, tiny work).
// ---------------------------------------------------------------------------
template <int CIN, int COUT, int WX, int WC, int COT, int XTT, bool CONTIG>
__global__ void __launch_bounds__(32 * WX * WC) k_convd(
    const float* __restrict__ in, float* __restrict__ out,
    const float* __restrict__ W, const float* __restrict__ mask, int D) {
    const int lane = threadIdx.x & 31;
    const int wrp = threadIdx.x >> 5;
    const int wc = wrp % WC;
    const int wx = wrp / WC;
    const int z = blockIdx.z, y = blockIdx.y;
    const int x0 = blockIdx.x * (WX * XTT) + wx * XTT;
    const int co0 = CONTIG ? (lane + 32 * wc) * COT : (lane + 32 * wc);

    float acc[XTT][COT];
#pragma unroll
    for (int i = 0; i < XTT; i++)
#pragma unroll
        for (int j = 0; j < COT; j++) acc[i][j] = 0.f;

#pragma unroll 1
    for (int r = 0; r < 9; r++) {
        const int dz = r / 3 - 1, dy = r % 3 - 1;
        const int zz = z + dz, yy = y + dy;
        if ((unsigned)zz >= (unsigned)D || (unsigned)yy >= (unsigned)D) continue;
        const float* rowp = in + (size_t)((zz * D + yy) * D) * CIN;
#pragma unroll 1
        for (int dx = 0; dx < 3; dx++) {
            const float* wp = W + (size_t)((r * 3 + dx) * CIN) * COUT + co0;
            int offs[XTT];
            bool val[XTT];
#pragma unroll
            for (int i = 0; i < XTT; i++) {
                int gx = x0 + i + dx - 1;
                val[i] = (unsigned)gx < (unsigned)D;
                offs[i] = gx * CIN;
            }
#pragma unroll 1
            for (int c = 0; c < CIN; c += 4) {
                float wv[4][COT];
#pragma unroll
                for (int q = 0; q < 4; q++) {
                    if (CONTIG && COT == 2) {
                        float2 t = *reinterpret_cast<const float2*>(wp + (c + q) * COUT);
                        wv[q][0] = t.x;
                        wv[q][1] = t.y;
                    } else {
#pragma unroll
                        for (int j = 0; j < COT; j++)
                            wv[q][j] = wp[(c + q) * COUT + j * 32 * WC];
                    }
                }
#pragma unroll
                for (int i = 0; i < XTT; i++) {
                    float4 a = val[i]
                        ? *reinterpret_cast<const float4*>(rowp + offs[i] + c)
                        : make_float4(0.f, 0.f, 0.f, 0.f);
#pragma unroll
                    for (int j = 0; j < COT; j++) {
                        acc[i][j] = fmaf(a.x, wv[0][j], acc[i][j]);
                        acc[i][j] = fmaf(a.y, wv[1][j], acc[i][j]);
                        acc[i][j] = fmaf(a.z, wv[2][j], acc[i][j]);
                        acc[i][j] = fmaf(a.w, wv[3][j], acc[i][j]);
                    }
                }
            }
        }
    }

    const int vb = (z * D + y) * D;
#pragma unroll
    for (int i = 0; i < XTT; i++) {
        int gx = x0 + i;
        float m = mask[vb + gx];
        float* op = out + (size_t)(vb + gx) * COUT + co0;
        if (CONTIG && COT == 2) {
            float2 t;
            t.x = acc[i][0] * m;
            t.y = acc[i][1] * m;
            *reinterpret_cast<float2*>(op) = t;
        } else {
#pragma unroll
            for (int j = 0; j < COT; j++) op[j * 32 * WC] = acc[i][j] * m;
        }
    }
}

// ---------------------------------------------------------------------------
// Masked 2x2x2 max pool.
// ---------------------------------------------------------------------------
__global__ void k_pool(const float* __restrict__ in, const float* __restrict__ im,
                       float* __restrict__ out, float* __restrict__ om,
                       int Do, int C) {
    int idx = blockIdx.x * blockDim.x + threadIdx.x;
    int total = Do * Do * Do * C;
    if (idx >= total) return;
    int c = idx % C;
    int v = idx / C;
    int xo = v % Do;
    int yo = (v / Do) % Do;
    int zo = v / (Do * Do);
    int Di = Do * 2;
    float best = -3.4e38f;
    bool any = false;
#pragma unroll
    for (int a = 0; a < 2; a++)
#pragma unroll
        for (int b = 0; b < 2; b++)
#pragma unroll
            for (int d = 0; d < 2; d++) {
                int vi = ((2 * zo + a) * Di + (2 * yo + b)) * Di + (2 * xo + d);
                if (im[vi] > 0.f) {
                    any = true;
                    float t = in[vi * C + c];
                    best = t > best ? t : best;
                }
            }
    out[v * C + c] = any ? best : 0.f;
    if (c == 0) om[v] = any ? 1.f : 0.f;
}

// ---------------------------------------------------------------------------
extern "C" void kernel_launch(void* const* d_in, const int* in_sizes, int n_in,
                              void* d_out, int out_size) {
    const float* feat = (const float*)d_in[0];
    const int* coors = (const int*)d_in[1];
    const float* W[14];
    for (int i = 0; i < 14; i++) W[i] = (const float*)d_in[2 + i];

    float *A, *B, *MA, *MB;
    int* OWN;
    cudaGetSymbolAddress((void**)&A, g_bufA);
    cudaGetSymbolAddress((void**)&B, g_bufB);
    cudaGetSymbolAddress((void**)&MA, g_maskA);
    cudaGetSymbolAddress((void**)&MB, g_maskB);
    cudaGetSymbolAddress((void**)&OWN, g_owner);

    const int N = in_sizes[0] / 3;
    const int sb = (N + 39) / 40;  // 40 voxels per block

    k_reset<<<(VOL0 + 255) / 256, 256>>>(OWN);
    k_scatter<<<(N + 255) / 256, 256>>>(coors, N, OWN);
    k_build<<<(VOL0 + 255) / 256, 256>>>(OWN, feat, A, MA);

    // Level 0 (D=64): conv0 output buffer must be zeroed (conv1 gathers it).
    const int n4 = VOL0 * 64 / 4;
    k_fill0<<<(n4 + 255) / 256, 256>>>((float4*)B, n4);
    k_conv_s0<<<sb, 128>>>(A, B, W[0]);
    k_conv_s64<<<sb, 128>>>(B, A, W[1]);  // out only read via masked pool
    k_pool<<<(32 * 32 * 32 * 64 + 255) / 256, 256>>>(A, MA, B, MB, 32, 64);

    // D=32 (packed)
    k_convp<64, 96, 4, 1, 3, 4, false><<<dim3(1, 32, 32), 128>>>(B, A, W[2], MB, 32);
    k_convp<96, 96, 4, 1, 3, 4, false><<<dim3(1, 32, 32), 128>>>(A, B, W[3], MB, 32);
    k_pool<<<(16 * 16 * 16 * 96 + 255) / 256, 256>>>(B, MB, A, MA, 16, 96);

    // D=16 (packed)
    k_convp<96, 128, 2, 2, 2, 4, true><<<dim3(1, 16, 16), 128>>>(A, B, W[4], MA, 16);
    k_convp<128, 128, 2, 2, 2, 4, true><<<dim3(1, 16, 16), 128>>>(B, A, W[5], MA, 16);
    k_pool<<<(8 * 8 * 8 * 128 + 255) / 256, 256>>>(A, MA, B, MB, 8, 128);

    // D=8 (scalar tail)
    k_convd<128, 160, 1, 5, 1, 1, false><<<dim3(8, 8, 8), 160>>>(B, A, W[6], MB, 8);
    k_convd<160, 160, 1, 5, 1, 1, false><<<dim3(8, 8, 8), 160>>>(A, B, W[7], MB, 8);
    k_pool<<<(4 * 4 * 4 * 160 + 255) / 256, 256>>>(B, MB, A, MA, 4, 160);

    // D=4
    k_convd<160, 192, 1, 3, 2, 1, true><<<dim3(4, 4, 4), 96>>>(A, B, W[8], MA, 4);
    k_convd<192, 192, 1, 3, 2, 1, true><<<dim3(4, 4, 4), 96>>>(B, A, W[9], MA, 4);
    k_pool<<<(2 * 2 * 2 * 192 + 255) / 256, 256>>>(A, MA, B, MB, 2, 192);

    // D=2
    k_convd<192, 224, 1, 7, 1, 1, false><<<dim3(2, 2, 2), 224>>>(B, A, W[10], MB, 2);
    k_convd<224, 224, 1, 7, 1, 1, false><<<dim3(2, 2, 2), 224>>>(A, B, W[11], MB, 2);
    k_pool<<<(1 * 224 + 255) / 256, 256>>>(B, MB, A, MA, 1, 224);

    // D=1 -> final output straight into d_out
    k_convd<224, 256, 1, 4, 2, 1, true><<<dim3(1, 1, 1), 128>>>(A, B, W[12], MA, 1);
    k_convd<256, 256, 1, 4, 2, 1, true><<<dim3(1, 1, 1), 128>>>(B, (float*)d_out, W[13], MA, 1);
}